// round 3
// baseline (speedup 1.0000x reference)
#include <cuda_runtime.h>
#include <cuda_bf16.h>

// FuzzyLayer: out[b,s,d*I+i] = exp(-(x[b,s,i]-mu[d,i])^2 / sigma[d,i])
// B=16, S=2048, I=256, D=8.  256 MB write + 32 MB read -> HBM-write-bound.
//
// R2 -> R3 change: occupancy 3 -> 4 CTAs/SM (100% warp slots) by forcing
// <=32 regs (__launch_bounds__(512,4)); x prefetch batch shrunk 4 -> 2 rows
// to cut payload registers. ROWS 8 -> 16 per block (128 KB contiguous
// writes per block for DRAM page locality).
// Kept: thread owns fixed column group (params in regs), all 8 'd' groups
// co-resident in CTA (x reuse via L1), float4 traffic, __stcs streaming stores.

static constexpr int BATCH = 16;
static constexpr int SEQ   = 2048;
static constexpr int BS    = BATCH * SEQ;   // 32768 rows
static constexpr int ROWS  = 16;            // rows per block (8 batches of 2)

__device__ __forceinline__ float ex2_approx(float t) {
    float r;
    asm("ex2.approx.ftz.f32 %0, %1;" : "=f"(r) : "f"(t));
    return r;
}

__global__ void __launch_bounds__(512, 4)
fuzzy_kernel(const float4* __restrict__ x4,
             const float4* __restrict__ fp4,
             float4* __restrict__ out4)
{
    const int c4 = threadIdx.x;      // 0..511 : output float4 column group
    const int i4 = c4 & 63;          // float4 group within I
    const int d  = c4 >> 6;          // fuzzy degree

    // fuzzy_params (2048,2) row-major: fp[2j]=mu_j, fp[2j+1]=sigma_j, j=d*256+i.
    const float4 p0 = fp4[d * 128 + i4 * 2];
    const float4 p1 = fp4[d * 128 + i4 * 2 + 1];

    const float L2E = 1.4426950408889634f;
    const float mu0 = p0.x, rs0 = -L2E / p0.y;
    const float mu1 = p0.z, rs1 = -L2E / p0.w;
    const float mu2 = p1.x, rs2 = -L2E / p1.y;
    const float mu3 = p1.z, rs3 = -L2E / p1.w;

    const int bs0 = blockIdx.x * ROWS;
    const float4* __restrict__ xin  = x4   + bs0 * 64 + i4;
    float4* __restrict__       oout = out4 + bs0 * 512 + c4;

#pragma unroll 1
    for (int r = 0; r < ROWS; r += 2) {
        // 2 independent x loads in flight (8 payload regs)
        float4 xa = __ldg(xin);
        float4 xb = __ldg(xin + 64);
        xin += 128;

        {
            float t0 = xa.x - mu0, t1 = xa.y - mu1, t2 = xa.z - mu2, t3 = xa.w - mu3;
            t0 = t0 * t0 * rs0; t1 = t1 * t1 * rs1;
            t2 = t2 * t2 * rs2; t3 = t3 * t3 * rs3;
            float4 o;
            o.x = ex2_approx(t0); o.y = ex2_approx(t1);
            o.z = ex2_approx(t2); o.w = ex2_approx(t3);
            __stcs(oout, o);
        }
        {
            float t0 = xb.x - mu0, t1 = xb.y - mu1, t2 = xb.z - mu2, t3 = xb.w - mu3;
            t0 = t0 * t0 * rs0; t1 = t1 * t1 * rs1;
            t2 = t2 * t2 * rs2; t3 = t3 * t3 * rs3;
            float4 o;
            o.x = ex2_approx(t0); o.y = ex2_approx(t1);
            o.z = ex2_approx(t2); o.w = ex2_approx(t3);
            __stcs(oout + 512, o);
        }
        oout += 1024;
    }
}

extern "C" void kernel_launch(void* const* d_in, const int* in_sizes, int n_in,
                              void* d_out, int out_size)
{
    const float4* x4  = (const float4*)d_in[0];   // x: (16,2048,256) f32
    const float4* fp4 = (const float4*)d_in[1];   // fuzzy_params: (2048,2) f32
    float4* out4      = (float4*)d_out;           // (16,2048,2048) f32

    fuzzy_kernel<<<BS / ROWS, 512>>>(x4, fp4, out4);
}

// round 4
// speedup vs baseline: 1.0829x; 1.0829x over previous
#include <cuda_runtime.h>
#include <cuda_bf16.h>

// FuzzyLayer: out[b,s,d*I+i] = exp(-(x[b,s,i]-mu[d,i])^2 / sigma[d,i])
// B=16, S=2048, I=256, D=8.  256 MB write + 32 MB read -> HBM-write-bound.
//
// R3 -> R4 change (model revision: occupancy was NOT the lever; store stream
// stalling on x-load latency was):
//  - Stage each block's 32 x-rows (32 KB) into SMEM via one cooperative
//    high-MLP fill + single __syncthreads. Compute/store loop then depends
//    only on LDS (29 cyc) -> stores issue continuously.
//  - Math refactored to polynomial: exp2((rs*x + c1)*x + c0), c1=-2*rs*mu,
//    c0=rs*mu^2 -> 2 FFMA + 1 MUFU per element (was 3 flops + MUFU).
// Kept: thread owns fixed output column group (coeffs in regs), all 8 'd'
// groups co-resident per CTA, float4 traffic, __stcs streaming stores.

static constexpr int BATCH = 16;
static constexpr int SEQ   = 2048;
static constexpr int BS    = BATCH * SEQ;   // 32768 rows
static constexpr int ROWS  = 32;            // rows per block (32 KB smem)

__device__ __forceinline__ float ex2_approx(float t) {
    float r;
    asm("ex2.approx.ftz.f32 %0, %1;" : "=f"(r) : "f"(t));
    return r;
}

__global__ void __launch_bounds__(512, 4)
fuzzy_kernel(const float4* __restrict__ x4,
             const float4* __restrict__ fp4,
             float4* __restrict__ out4)
{
    __shared__ float4 sx[ROWS * 64];         // 32 KB: ROWS rows of x (256 f32)

    const int tid = threadIdx.x;
    const int c4  = tid;                      // output float4 column group
    const int i4  = c4 & 63;                  // float4 group within I
    const int d   = c4 >> 6;                  // fuzzy degree

    // fuzzy_params (2048,2) row-major: fp[2j]=mu_j, fp[2j+1]=sigma_j, j=d*256+i.
    const float4 p0 = fp4[d * 128 + i4 * 2];
    const float4 p1 = fp4[d * 128 + i4 * 2 + 1];

    const float L2E = 1.4426950408889634f;
    // exponent(x) = rs*(x-mu)^2 = (rs*x + c1)*x + c0
    const float a0 = -L2E / p0.y, b0 = -2.f * a0 * p0.x, e0 = a0 * p0.x * p0.x;
    const float a1 = -L2E / p0.w, b1 = -2.f * a1 * p0.z, e1 = a1 * p0.z * p0.z;
    const float a2 = -L2E / p1.y, b2 = -2.f * a2 * p1.x, e2 = a2 * p1.x * p1.x;
    const float a3 = -L2E / p1.w, b3 = -2.f * a3 * p1.z, e3 = a3 * p1.z * p1.z;

    const int bs0 = blockIdx.x * ROWS;

    // Cooperative fill: 2048 float4 / 512 threads = 4 per thread (MLP=4).
    const float4* __restrict__ src = x4 + bs0 * 64;
#pragma unroll
    for (int k = 0; k < ROWS * 64 / 512; ++k)
        sx[tid + k * 512] = src[tid + k * 512];
    __syncthreads();

    float4* __restrict__ oout = out4 + bs0 * 512 + c4;

#pragma unroll 4
    for (int r = 0; r < ROWS; ++r) {
        const float4 xv = sx[r * 64 + i4];

        float4 o;
        o.x = ex2_approx(fmaf(fmaf(a0, xv.x, b0), xv.x, e0));
        o.y = ex2_approx(fmaf(fmaf(a1, xv.y, b1), xv.y, e1));
        o.z = ex2_approx(fmaf(fmaf(a2, xv.z, b2), xv.z, e2));
        o.w = ex2_approx(fmaf(fmaf(a3, xv.w, b3), xv.w, e3));

        __stcs(oout + r * 512, o);
    }
}

extern "C" void kernel_launch(void* const* d_in, const int* in_sizes, int n_in,
                              void* d_out, int out_size)
{
    const float4* x4  = (const float4*)d_in[0];   // x: (16,2048,256) f32
    const float4* fp4 = (const float4*)d_in[1];   // fuzzy_params: (2048,2) f32
    float4* out4      = (float4*)d_out;           // (16,2048,2048) f32

    fuzzy_kernel<<<BS / ROWS, 512>>>(x4, fp4, out4);   // 1024 blocks
}